// round 7
// baseline (speedup 1.0000x reference)
#include <cuda_runtime.h>

#define T_STEPS 512
#define HID 64

typedef unsigned long long ull;

// packed fp32x2 FMA: d.lo += a.lo*b.lo ; d.hi += a.hi*b.hi  (Blackwell FFMA2, PTX-only)
__device__ __forceinline__ void fma2(ull &d, ull a, ull b) {
    asm("fma.rn.f32x2 %0, %1, %2, %0;" : "+l"(d) : "l"(a), "l"(b));
}
__device__ __forceinline__ ull add2(ull a, ull b) {
    ull r;
    asm("add.rn.f32x2 %0, %1, %2;" : "=l"(r) : "l"(a), "l"(b));
    return r;
}
__device__ __forceinline__ float hsum2(ull v) {
    float lo, hi;
    asm("mov.b64 {%0,%1}, %2;" : "=f"(lo), "=f"(hi) : "l"(v));
    return lo + hi;
}

// tanh(x) = 1 - 2/(e^{2x}+1): MUFU.EX2 + MUFU.RCP path, abs err ~1e-7.
__device__ __forceinline__ float tanh_fast(float x) {
    float xc = fminf(fmaxf(x, -10.0f), 10.0f);
    float e  = __expf(xc + xc);
    return 1.0f - __fdividef(2.0f, e + 1.0f);
}

// ROW-SPLIT: CTA = 2 warps, 2 batches. Thread (w, lane) owns W_hh row (32w+lane)
// (64 regs) and computes that row's full dot for BOTH batches each step.
// Double-buffered h + ONE __syncthreads per step, zero exchange traffic.
// 2048 warps -> 3.46 warps/SMSP, single wave, ~100 regs.
// R6 bug fixed: x staged into ONE contiguous sx[2][T] array (the 4KB block copy
// previously assumed sxA/sxB adjacency and ran off the shared allocation).
__global__ void rnn_rowsplit_kernel(const float* __restrict__ x,
                                    const float* __restrict__ W_ih,
                                    const float* __restrict__ W_hh,
                                    const float* __restrict__ b_ih,
                                    const float* __restrict__ b_hh,
                                    const float* __restrict__ fc_w,
                                    const float* __restrict__ fc_b,
                                    float* __restrict__ out)
{
    __shared__ __align__(16) float sx[2][T_STEPS];   // [batch][t], contiguous 4KB
    __shared__ __align__(16) float hsh[2][2][HID];   // [pingpong][batch][row]

    const int tid  = threadIdx.x;        // 0..63
    const int lane = tid & 31;
    const int row  = tid;                // warp0 -> rows 0..31, warp1 -> rows 32..63
    const int b0   = 2 * blockIdx.x;

    // This thread's W_hh row, as f32x2 j-pairs (64 regs).
    ull wreg[32];
    {
        const ull* wr = reinterpret_cast<const ull*>(W_hh + row * HID);
#pragma unroll
        for (int p = 0; p < 32; ++p) wreg[p] = wr[p];
    }

    const float wih  = W_ih[row];
    const float bias = b_ih[row] + b_hh[row];

    // Stage both x sequences (I=1 => 1024 contiguous floats = 256 float4).
    {
        const float4* xg = reinterpret_cast<const float4*>(x + (size_t)b0 * T_STEPS);
        float4* s = reinterpret_cast<float4*>(&sx[0][0]);
#pragma unroll
        for (int i = 0; i < 4; ++i) s[tid + 64 * i] = xg[tid + 64 * i];
    }

    // h(-1) = 0 in buffer 0.
    hsh[0][0][row] = 0.0f;
    hsh[0][1][row] = 0.0f;
    __syncthreads();

#pragma unroll 1
    for (int t = 0; t < T_STEPS; ++t) {
        const int cur = t & 1;
        const ulonglong2* hA = reinterpret_cast<const ulonglong2*>(hsh[cur][0]);
        const ulonglong2* hB = reinterpret_cast<const ulonglong2*>(hsh[cur][1]);

        // Full-K dot for my row, both batches: 4 independent FFMA2 chains, depth 16.
        ull aA0 = 0, aA1 = 0, aB0 = 0, aB1 = 0;
#pragma unroll
        for (int k = 0; k < 16; ++k) {
            ulonglong2 ha = hA[k];                  // LDS.128 broadcast
            ulonglong2 hb = hB[k];
            fma2(aA0, ha.x, wreg[2 * k]);  fma2(aA1, ha.y, wreg[2 * k + 1]);
            fma2(aB0, hb.x, wreg[2 * k]);  fma2(aB1, hb.y, wreg[2 * k + 1]);
        }
        float sA = hsum2(add2(aA0, aA1)) + fmaf(sx[0][t], wih, bias);
        float sB = hsum2(add2(aB0, aB1)) + fmaf(sx[1][t], wih, bias);
        hsh[cur ^ 1][0][row] = tanh_fast(sA);
        hsh[cur ^ 1][1][row] = tanh_fast(sB);
        __syncthreads();   // reads of h[cur] precede the bar; writes target h[cur^1]
    }

    // T even -> final h in buffer 0. Warp 0 reduces FC for both batches.
    if (tid < 32) {
        const float fw0 = fc_w[lane], fw1 = fc_w[lane + 32];
        float vA = fmaf(hsh[0][0][lane], fw0, hsh[0][0][lane + 32] * fw1);
        float vB = fmaf(hsh[0][1][lane], fw0, hsh[0][1][lane + 32] * fw1);
#pragma unroll
        for (int o = 16; o; o >>= 1) {
            vA += __shfl_xor_sync(0xffffffffu, vA, o);
            vB += __shfl_xor_sync(0xffffffffu, vB, o);
        }
        if (lane == 0) {
            float fb = fc_b[0];
            out[b0]     = vA + fb;
            out[b0 + 1] = vB + fb;
        }
    }
}

extern "C" void kernel_launch(void* const* d_in, const int* in_sizes, int n_in,
                              void* d_out, int out_size)
{
    const float* x    = (const float*)d_in[0];  // [B, T, 1]
    const float* W_ih = (const float*)d_in[1];  // [64, 1]
    const float* W_hh = (const float*)d_in[2];  // [64, 64]
    const float* b_ih = (const float*)d_in[3];  // [64]
    const float* b_hh = (const float*)d_in[4];  // [64]
    const float* fc_w = (const float*)d_in[5];  // [1, 64]
    const float* fc_b = (const float*)d_in[6];  // [1]
    float* out = (float*)d_out;                 // [B, 1]

    int B = in_sizes[0] / T_STEPS;              // I == 1
    rnn_rowsplit_kernel<<<B / 2, 64>>>(x, W_ih, W_hh, b_ih, b_hh, fc_w, fc_b, out);
}

// round 8
// speedup vs baseline: 1.2004x; 1.2004x over previous
#include <cuda_runtime.h>

#define T_STEPS 512
#define HID 64

typedef unsigned long long ull;

// packed fp32x2 FMA: d.lo += a.lo*b.lo ; d.hi += a.hi*b.hi
// NOTE (measured R2-R7): FFMA2 rt_SMSP = 4 on sm_103a -> same MAC throughput as
// scalar FFMA; value is instruction-count/register savings only. We are at the
// fp32 roofline (4.3G MACs / 9472 MACs-per-cyc-chip ~= 252us).
__device__ __forceinline__ void fma2(ull &d, ull a, ull b) {
    asm("fma.rn.f32x2 %0, %1, %2, %0;" : "+l"(d) : "l"(a), "l"(b));
}
__device__ __forceinline__ ull add2(ull a, ull b) {
    ull r;
    asm("add.rn.f32x2 %0, %1, %2;" : "=l"(r) : "l"(a), "l"(b));
    return r;
}
__device__ __forceinline__ float hsum2(ull v) {
    float lo, hi;
    asm("mov.b64 {%0,%1}, %2;" : "=f"(lo), "=f"(hi) : "l"(v));
    return lo + hi;
}

// tanh(x) = 1 - 2/(2^(2*log2e*x)+1), clamp-free: x->+inf: e=inf, rcp->0, t->1;
// x->-inf: e->0, t->-1. MUFU.EX2 + MUFU.RCP, abs err ~1e-7.
__device__ __forceinline__ float tanh_fast(float x) {
    float e;
    asm("ex2.approx.f32 %0, %1;" : "=f"(e) : "f"(x * 2.885390082f)); // 2*log2(e)
    float r;
    asm("rcp.approx.f32 %0, %1;" : "=f"(r) : "f"(e + 1.0f));
    return fmaf(-2.0f, r, 1.0f);
}

// One warp, two batches (A, B), software-pipelined one step apart (R5 schedule):
// the tanh/hsum/STS tail of one batch hides under the other's 64-FFMA2 stream.
// W_hh rows (lane, lane+32) register-resident (128 regs), grid=1024, single wave.
__global__ void rnn_pipe_kernel(const float* __restrict__ x,
                                const float* __restrict__ W_ih,
                                const float* __restrict__ W_hh,
                                const float* __restrict__ b_ih,
                                const float* __restrict__ b_hh,
                                const float* __restrict__ fc_w,
                                const float* __restrict__ fc_b,
                                float* __restrict__ out)
{
    __shared__ __align__(16) float sxA[T_STEPS];
    __shared__ __align__(16) float sxB[T_STEPS];
    __shared__ __align__(16) float hA[HID];
    __shared__ __align__(16) float hB[HID];

    const int lane = threadIdx.x;        // lane owns output rows (lane, lane+32)
    const int b0   = 2 * blockIdx.x;     // batches A=b0, B=b0+1

    // W_hh rows `lane` and `lane+32` as f32x2 j-pairs (128 regs).
    ull w0[32], w1[32];
    {
        const ull* wr0 = reinterpret_cast<const ull*>(W_hh + lane * HID);
        const ull* wr1 = reinterpret_cast<const ull*>(W_hh + (lane + 32) * HID);
#pragma unroll
        for (int p = 0; p < 32; ++p) { w0[p] = wr0[p]; w1[p] = wr1[p]; }
    }

    const float wih0  = W_ih[lane];
    const float wih1  = W_ih[lane + 32];
    const float bias0 = b_ih[lane]      + b_hh[lane];
    const float bias1 = b_ih[lane + 32] + b_hh[lane + 32];

    // Stage both x sequences (I=1 => contiguous 512 floats each).
    {
        const float4* xg  = reinterpret_cast<const float4*>(x + (size_t)b0 * T_STEPS);
        float4* sA = reinterpret_cast<float4*>(sxA);
        float4* sB = reinterpret_cast<float4*>(sxB);
#pragma unroll
        for (int i = 0; i < 4; ++i) {
            sA[lane + 32 * i] = xg[lane + 32 * i];
            sB[lane + 32 * i] = xg[128 + lane + 32 * i];
        }
        __syncwarp();
    }

    // h_A(0) = tanh(xp_A(0)); B's pipeline starts with zero partials.
    hA[lane]      = tanh_fast(fmaf(sxA[0], wih0, bias0));
    hA[lane + 32] = tanh_fast(fmaf(sxA[0], wih1, bias1));
    ull B0a = 0, B0b = 0, B1a = 0, B1b = 0;
    __syncwarp();

    const ulonglong2* hpA = reinterpret_cast<const ulonglong2*>(hA);
    const ulonglong2* hpB = reinterpret_cast<const ulonglong2*>(hB);

#pragma unroll 1
    for (int t = 1; t < T_STEPS; ++t) {
        // region 1: FFMA(A,t) over h_A(t-1)  ||  tail h_B(t-1) from carried accB
        ull A0a = 0, A0b = 0, A1a = 0, A1b = 0;
#pragma unroll
        for (int k = 0; k < 16; ++k) {
            ulonglong2 h2 = hpA[k];                 // LDS.128 broadcast
            fma2(A0a, h2.x, w0[2 * k]);  fma2(A0b, h2.y, w0[2 * k + 1]);
            fma2(A1a, h2.x, w1[2 * k]);  fma2(A1b, h2.y, w1[2 * k + 1]);
        }
        {
            float xb = sxB[t - 1];
            hB[lane]      = tanh_fast(hsum2(add2(B0a, B0b)) + fmaf(xb, wih0, bias0));
            hB[lane + 32] = tanh_fast(hsum2(add2(B1a, B1b)) + fmaf(xb, wih1, bias1));
        }
        __syncwarp();

        // region 2: FFMA(B,t-1) over h_B(t-1)  ||  tail h_A(t) from accA
        B0a = 0; B0b = 0; B1a = 0; B1b = 0;
#pragma unroll
        for (int k = 0; k < 16; ++k) {
            ulonglong2 h2 = hpB[k];
            fma2(B0a, h2.x, w0[2 * k]);  fma2(B0b, h2.y, w0[2 * k + 1]);
            fma2(B1a, h2.x, w1[2 * k]);  fma2(B1b, h2.y, w1[2 * k + 1]);
        }
        {
            float xa = sxA[t];
            hA[lane]      = tanh_fast(hsum2(add2(A0a, A0b)) + fmaf(xa, wih0, bias0));
            hA[lane + 32] = tanh_fast(hsum2(add2(A1a, A1b)) + fmaf(xa, wih1, bias1));
        }
        __syncwarp();
    }

    // Epilogue: finalize h_B(T-1) from carried accB (registers).
    float xb = sxB[T_STEPS - 1];
    float hBf0 = tanh_fast(hsum2(add2(B0a, B0b)) + fmaf(xb, wih0, bias0));
    float hBf1 = tanh_fast(hsum2(add2(B1a, B1b)) + fmaf(xb, wih1, bias1));

    // Final FC: out[b] = sum_h hT[h]*fc_w[h] + fc_b
    const float fw0 = fc_w[lane], fw1 = fc_w[lane + 32];
    float vA = fmaf(hA[lane], fw0, hA[lane + 32] * fw1);
    float vB = fmaf(hBf0,     fw0, hBf1          * fw1);
#pragma unroll
    for (int o = 16; o; o >>= 1) {
        vA += __shfl_xor_sync(0xffffffffu, vA, o);
        vB += __shfl_xor_sync(0xffffffffu, vB, o);
    }
    if (lane == 0) {
        float fb = fc_b[0];
        out[b0]     = vA + fb;
        out[b0 + 1] = vB + fb;
    }
}

extern "C" void kernel_launch(void* const* d_in, const int* in_sizes, int n_in,
                              void* d_out, int out_size)
{
    const float* x    = (const float*)d_in[0];  // [B, T, 1]
    const float* W_ih = (const float*)d_in[1];  // [64, 1]
    const float* W_hh = (const float*)d_in[2];  // [64, 64]
    const float* b_ih = (const float*)d_in[3];  // [64]
    const float* b_hh = (const float*)d_in[4];  // [64]
    const float* fc_w = (const float*)d_in[5];  // [1, 64]
    const float* fc_b = (const float*)d_in[6];  // [1]
    float* out = (float*)d_out;                 // [B, 1]

    int B = in_sizes[0] / T_STEPS;              // I == 1
    rnn_pipe_kernel<<<B / 2, 32>>>(x, W_ih, W_hh, b_ih, b_hh, fc_w, fc_b, out);
}

// round 10
// speedup vs baseline: 1.9770x; 1.6470x over previous
#include <cuda_runtime.h>
#include <cuda_bf16.h>
#include <cstdint>

#define T_STEPS 512
#define HID 64
#define NB 8          // batches per CTA
#define KPAD 72       // bf16 elems per h-row: 144B = 36 words -> bank+4 per row (conflict-free B frags)

__device__ __forceinline__ float tanh_fast(float x) {
    float e; asm("ex2.approx.f32 %0, %1;" : "=f"(e) : "f"(x * 2.885390082f)); // 2*log2(e)
    float r; asm("rcp.approx.f32 %0, %1;" : "=f"(r) : "f"(e + 1.0f));
    return fmaf(-2.0f, r, 1.0f);
}

// split (a,b) into packed-bf16 hi and lo parts: w = hi + lo, |w-hi-lo| ~ 2^-17 |w|
__device__ __forceinline__ void split2(float a, float b, uint32_t &uhi, uint32_t &ulo) {
    __nv_bfloat16 ah = __float2bfloat16_rn(a), bh = __float2bfloat16_rn(b);
    float ar = a - __bfloat162float(ah), br = b - __bfloat162float(bh);
    __nv_bfloat16 al = __float2bfloat16_rn(ar), bl = __float2bfloat16_rn(br);
    uhi = ((uint32_t)__bfloat16_as_ushort(bh) << 16) | __bfloat16_as_ushort(ah);
    ulo = ((uint32_t)__bfloat16_as_ushort(bl) << 16) | __bfloat16_as_ushort(al);
}

// Ampere-style bf16 MMA, fp32 accumulate: arch-neutral PTX (works on plain sm_103).
__device__ __forceinline__ void mma16816(float d[4], const uint32_t a[4], uint32_t b0, uint32_t b1) {
    asm volatile("mma.sync.aligned.m16n8k16.row.col.f32.bf16.bf16.f32 "
        "{%0,%1,%2,%3}, {%4,%5,%6,%7}, {%8,%9}, {%0,%1,%2,%3};"
        : "+f"(d[0]), "+f"(d[1]), "+f"(d[2]), "+f"(d[3])
        : "r"(a[0]), "r"(a[1]), "r"(a[2]), "r"(a[3]), "r"(b0), "r"(b1));
}

// CTA: 4 warps x 32, 8 batches. Warp wid owns M-rows [16*wid, 16*wid+16).
// Per step: Z[64,8] = W[64,64] @ h[64,8] via 12 HMMA/warp (3-term bf16 split, fp32 acc),
// epilogue tanh + bf16-split h written to smem for next step's B fragments.
__global__ void __launch_bounds__(128, 2)
rnn_hmma_kernel(const float* __restrict__ x,
                const float* __restrict__ W_ih,
                const float* __restrict__ W_hh,
                const float* __restrict__ b_ih,
                const float* __restrict__ b_hh,
                const float* __restrict__ fc_w,
                const float* __restrict__ fc_b,
                float* __restrict__ out)
{
    __shared__ __align__(16) float sx[T_STEPS][NB];                 // x transposed [t][n], 16KB
    __shared__ __align__(16) __nv_bfloat16 hbuf[2][2][NB][KPAD];    // [pingpong][split][n][k]
    __shared__ float red[4][NB];

    const int tid  = threadIdx.x;
    const int lane = tid & 31, wid = tid >> 5;
    const int g = lane >> 2, q = lane & 3;       // fragment coords
    const int mb = wid * 16;
    const int r0 = mb + g, r1 = mb + g + 8;      // this thread's two M rows
    const int c0 = 2 * q, c1 = 2 * q + 1;        // this thread's two N cols (batches)
    const int b0 = blockIdx.x * NB;

    // ---- loop-invariant A fragments: W_hh rows r0/r1, hi+lo bf16 splits (32 regs) ----
    uint32_t Ahi[4][4], Alo[4][4];
#pragma unroll
    for (int kt = 0; kt < 4; ++kt) {
        int kb = kt * 16 + 2 * q;
        split2(W_hh[r0 * HID + kb],     W_hh[r0 * HID + kb + 1],     Ahi[kt][0], Alo[kt][0]);
        split2(W_hh[r1 * HID + kb],     W_hh[r1 * HID + kb + 1],     Ahi[kt][1], Alo[kt][1]);
        split2(W_hh[r0 * HID + kb + 8], W_hh[r0 * HID + kb + 9],     Ahi[kt][2], Alo[kt][2]);
        split2(W_hh[r1 * HID + kb + 8], W_hh[r1 * HID + kb + 9],     Ahi[kt][3], Alo[kt][3]);
    }

    const float wih0 = W_ih[r0],             wih1 = W_ih[r1];
    const float bi0  = b_ih[r0] + b_hh[r0],  bi1  = b_ih[r1] + b_hh[r1];
    const float fw0  = fc_w[r0],             fw1  = fc_w[r1];

    // ---- stage x transposed: sx[t][n]  (I=1 -> each batch is 512 contiguous floats) ----
    {
        const float4* xg = reinterpret_cast<const float4*>(x + (size_t)b0 * T_STEPS);
        for (int i = tid; i < NB * (T_STEPS / 4); i += 128) {
            int bb = i >> 7, t4 = (i & 127) * 4;
            float4 v = xg[(i >> 7) * 128 + (i & 127)];
            sx[t4 + 0][bb] = v.x; sx[t4 + 1][bb] = v.y;
            sx[t4 + 2][bb] = v.z; sx[t4 + 3][bb] = v.w;
        }
    }
    __syncthreads();

    // ---- t=0: h(0) = tanh(x*W_ih + bias) -> write split h into hbuf[1] ----
    float h0, h1, h2, h3;
    {
        float xa = sx[0][c0], xb = sx[0][c1];
        h0 = tanh_fast(fmaf(wih0, xa, bi0));  h1 = tanh_fast(fmaf(wih0, xb, bi0));
        h2 = tanh_fast(fmaf(wih1, xa, bi1));  h3 = tanh_fast(fmaf(wih1, xb, bi1));
    }
#pragma unroll 1
    for (int init = 0; init < 1; ++init) {
        __nv_bfloat16 vhi, vlo;
        float hv[4] = {h0, h1, h2, h3};
        int   nn[4] = {c0, c1, c0, c1};
        int   mm[4] = {r0, r0, r1, r1};
#pragma unroll
        for (int i = 0; i < 4; ++i) {
            vhi = __float2bfloat16_rn(hv[i]);
            vlo = __float2bfloat16_rn(hv[i] - __bfloat162float(vhi));
            hbuf[1][0][nn[i]][mm[i]] = vhi;
            hbuf[1][1][nn[i]][mm[i]] = vlo;
        }
    }
    __syncthreads();

    // ---- recurrence: iteration t reads hbuf[t&1], writes hbuf[(t+1)&1] ----
#pragma unroll 1
    for (int t = 1; t < T_STEPS; ++t) {
        const int cur = t & 1, nxt = cur ^ 1;

        uint32_t Bhi[4][2], Blo[4][2];
#pragma unroll
        for (int kt = 0; kt < 4; ++kt) {
            int kb = kt * 16 + 2 * q;
            Bhi[kt][0] = *reinterpret_cast<const uint32_t*>(&hbuf[cur][0][g][kb]);
            Bhi[kt][1] = *reinterpret_cast<const uint32_t*>(&hbuf[cur][0][g][kb + 8]);
            Blo[kt][0] = *reinterpret_cast<const uint32_t*>(&hbuf[cur][1][g][kb]);
            Blo[kt][1] = *reinterpret_cast<const uint32_t*>(&hbuf[cur][1][g][kb + 8]);
        }

        float dA[4] = {0, 0, 0, 0}, dB[4] = {0, 0, 0, 0}, dC[4] = {0, 0, 0, 0};
#pragma unroll
        for (int kt = 0; kt < 4; ++kt) {
            mma16816(dA, Ahi[kt], Bhi[kt][0], Bhi[kt][1]);   // Whi * h_hi
            mma16816(dB, Ahi[kt], Blo[kt][0], Blo[kt][1]);   // Whi * h_lo
            mma16816(dC, Alo[kt], Bhi[kt][0], Bhi[kt][1]);   // Wlo * h_hi
        }

        float2 xv = *reinterpret_cast<const float2*>(&sx[t][c0]);
        h0 = tanh_fast(dA[0] + dB[0] + dC[0] + fmaf(wih0, xv.x, bi0));  // (r0, c0)
        h1 = tanh_fast(dA[1] + dB[1] + dC[1] + fmaf(wih0, xv.y, bi0));  // (r0, c1)
        h2 = tanh_fast(dA[2] + dB[2] + dC[2] + fmaf(wih1, xv.x, bi1));  // (r1, c0)
        h3 = tanh_fast(dA[3] + dB[3] + dC[3] + fmaf(wih1, xv.y, bi1));  // (r1, c1)

        {
            float hv[4] = {h0, h1, h2, h3};
            int   nn[4] = {c0, c1, c0, c1};
            int   mm[4] = {r0, r0, r1, r1};
#pragma unroll
            for (int i = 0; i < 4; ++i) {
                __nv_bfloat16 vhi = __float2bfloat16_rn(hv[i]);
                __nv_bfloat16 vlo = __float2bfloat16_rn(hv[i] - __bfloat162float(vhi));
                hbuf[nxt][0][nn[i]][mm[i]] = vhi;
                hbuf[nxt][1][nn[i]][mm[i]] = vlo;
            }
        }
        __syncthreads();
    }

    // ---- FC on h(T-1) held in regs: out[n] = sum_m fc_w[m] h[m][n] + fc_b ----
    float p0 = fmaf(fw0, h0, fw1 * h2);   // n = c0
    float p1 = fmaf(fw0, h1, fw1 * h3);   // n = c1
#pragma unroll
    for (int o = 4; o < 32; o <<= 1) {    // reduce over g-groups (lanes with same q)
        p0 += __shfl_xor_sync(0xffffffffu, p0, o);
        p1 += __shfl_xor_sync(0xffffffffu, p1, o);
    }
    if (lane < 4) { red[wid][c0] = p0; red[wid][c1] = p1; }
    __syncthreads();
    if (tid < NB)
        out[b0 + tid] = red[0][tid] + red[1][tid] + red[2][tid] + red[3][tid] + fc_b[0];
}

extern "C" void kernel_launch(void* const* d_in, const int* in_sizes, int n_in,
                              void* d_out, int out_size)
{
    const float* x    = (const float*)d_in[0];  // [B, T, 1]
    const float* W_ih = (const float*)d_in[1];  // [64, 1]
    const float* W_hh = (const float*)d_in[2];  // [64, 64]
    const float* b_ih = (const float*)d_in[3];  // [64]
    const float* b_hh = (const float*)d_in[4];  // [64]
    const float* fc_w = (const float*)d_in[5];  // [1, 64]
    const float* fc_b = (const float*)d_in[6];  // [1]
    float* out = (float*)d_out;                 // [B, 1]

    int B = in_sizes[0] / T_STEPS;              // I == 1
    rnn_hmma_kernel<<<B / NB, 128>>>(x, W_ih, W_hh, b_ih, b_hh, fc_w, fc_b, out);
}